// round 2
// baseline (speedup 1.0000x reference)
#include <cuda_runtime.h>
#include <math.h>

#define B_GRAPHS 65536
#define NPG 9
#define DIN 11
#define D 64
#define GB 8                      // graphs per block-iteration
#define NODES (GB * NPG)          // 72
#define THREADS 256
#define HSTRIDE 68                // padded row stride for h (bank-conflict-free head reads)
#define NITER (B_GRAPHS / GB)     // 8192

// biased_softplus bias: log(expm1(1.0)) = log(e - 1)
#define SOFTPLUS_BIAS 0.54132485461291809f

struct Smem {
    float WTin[12][D];      // [k][d], k=11 row zero-padded
    float WT1rel[D][D];     // [k][d]
    float WTd1[D][D];       // W1_root - W1_rel, [k][d]
    float WT2rel[D][D];
    float WTd2[D][D];
    float Wh[8][65][2];     // head weights, j-stride padded (65*2=130 floats)
    float b_in[D], b1v[D], b2v[D];
    float bh[8][2];
    float h[NODES][HSTRIDE];
    float xs[NODES][12];    // x tile, col 11 zero-padded
    float hs[GB][HSTRIDE];  // per-graph sums
    float Sg[GB][HSTRIDE];  // per-graph S = b + hs @ W_rel^T  (per dim)
};

__device__ __forceinline__ float tanh_fast(float x) {
    float y;
    asm("tanh.approx.f32 %0, %1;" : "=f"(y) : "f"(x));
    return y;
}

__device__ __forceinline__ void gnn_layer(Smem* sm, int tid, int d, int quad,
                                          const float (*WTrel)[D],
                                          const float (*WTd)[D],
                                          const float* bvec)
{
    // --- per-graph sums hs[g][k] = sum over 9 nodes of h ---
    if (tid < GB * 16) {
        int g = tid >> 4, kq = tid & 15;
        float4 s = make_float4(0.f, 0.f, 0.f, 0.f);
        #pragma unroll
        for (int n = 0; n < NPG; n++) {
            float4 v = *(const float4*)&sm->h[g * NPG + n][kq * 4];
            s.x += v.x; s.y += v.y; s.z += v.z; s.w += v.w;
        }
        *(float4*)&sm->hs[g][kq * 4] = s;
    }
    __syncthreads();

    // --- S[g][d] = b[d] + sum_k hs[g][k] * Wrel[d][k]  (each quad: 2 graphs) ---
    {
        int ga = quad * 2, gb2 = quad * 2 + 1;
        float bb = bvec[d];
        float sA = bb, sB = bb;
        #pragma unroll
        for (int kc = 0; kc < 4; kc++) {
            float w[16];
            #pragma unroll
            for (int k = 0; k < 16; k++) w[k] = WTrel[kc * 16 + k][d];
            const float4* pa = (const float4*)&sm->hs[ga][kc * 16];
            const float4* pb = (const float4*)&sm->hs[gb2][kc * 16];
            #pragma unroll
            for (int q = 0; q < 4; q++) {
                float4 va = pa[q], vb = pb[q];
                sA += va.x * w[4*q] + va.y * w[4*q+1] + va.z * w[4*q+2] + va.w * w[4*q+3];
                sB += vb.x * w[4*q] + vb.y * w[4*q+1] + vb.z * w[4*q+2] + vb.w * w[4*q+3];
            }
        }
        sm->Sg[ga][d] = sA;
        sm->Sg[gb2][d] = sB;
    }
    __syncthreads();

    // --- per-node: out = tanh(S[g] + h[n] @ (Wroot - Wrel)^T) ---
    float acc[18];
    #pragma unroll
    for (int r = 0; r < 18; r++) {
        int g = quad * 2 + (r >= 9 ? 1 : 0);
        acc[r] = sm->Sg[g][d];
    }
    #pragma unroll
    for (int kc = 0; kc < 4; kc++) {
        float w[16];
        #pragma unroll
        for (int k = 0; k < 16; k++) w[k] = WTd[kc * 16 + k][d];
        #pragma unroll
        for (int r = 0; r < 18; r++) {
            const float4* hp = (const float4*)&sm->h[quad * 18 + r][kc * 16];
            #pragma unroll
            for (int q = 0; q < 4; q++) {
                float4 v = hp[q];
                acc[r] += v.x * w[4*q] + v.y * w[4*q+1] + v.z * w[4*q+2] + v.w * w[4*q+3];
            }
        }
    }
    #pragma unroll
    for (int r = 0; r < 18; r++) acc[r] = tanh_fast(acc[r]);
    __syncthreads();   // all reads of h done before overwrite
    #pragma unroll
    for (int r = 0; r < 18; r++) sm->h[quad * 18 + r][d] = acc[r];
    __syncthreads();
}

__global__ __launch_bounds__(THREADS, 2)
void gnn_kernel(const float* __restrict__ x,
                const float* __restrict__ gW_in,  const float* __restrict__ gb_in,
                const float* __restrict__ gW1rel, const float* __restrict__ gb1,
                const float* __restrict__ gW1root,
                const float* __restrict__ gW2rel, const float* __restrict__ gb2,
                const float* __restrict__ gW2root,
                const float* __restrict__ gWhead, const float* __restrict__ gbhead,
                float* __restrict__ out)
{
    extern __shared__ char smem_raw[];
    Smem* sm = reinterpret_cast<Smem*>(smem_raw);
    const int tid = threadIdx.x;
    const int d = tid & 63;
    const int quad = tid >> 6;

    // ---- one-time weight staging (transposed) ----
    for (int i = tid; i < D * D; i += THREADS) {
        int dd = i >> 6, k = i & 63;
        float r1 = gW1rel[i];
        sm->WT1rel[k][dd] = r1;
        sm->WTd1[k][dd]  = gW1root[i] - r1;
        float r2 = gW2rel[i];
        sm->WT2rel[k][dd] = r2;
        sm->WTd2[k][dd]  = gW2root[i] - r2;
    }
    for (int i = tid; i < D * 12; i += THREADS) {
        int dd = i & 63, k = i >> 6;
        sm->WTin[k][dd] = (k < DIN) ? gW_in[dd * DIN + k] : 0.f;
    }
    for (int i = tid; i < 8 * D * 2; i += THREADS) {
        int j = i >> 7, r = i & 127, k = r >> 1, o = r & 1;
        sm->Wh[j][k][o] = gWhead[i];
    }
    if (tid < D) { sm->b_in[tid] = gb_in[tid]; sm->b1v[tid] = gb1[tid]; sm->b2v[tid] = gb2[tid]; }
    if (tid < 16) sm->bh[tid >> 1][tid & 1] = gbhead[tid];
    __syncthreads();

    for (int gb = blockIdx.x; gb < NITER; gb += gridDim.x) {
        const long long g0 = (long long)gb * GB;
        __syncthreads();  // protect h / xs from previous iteration's readers

        // ---- load x tile (72 nodes x 11, zero-padded to 12) ----
        const float* xg = x + g0 * NPG * DIN;
        for (int i = tid; i < NODES * 12; i += THREADS) {
            int n = i / 12, k = i - n * 12;
            sm->xs[n][k] = (k < DIN) ? xg[n * DIN + k] : 0.f;
        }
        __syncthreads();

        // ---- input layer: h = x @ W_in^T + b_in (no activation) ----
        {
            float win[12];
            #pragma unroll
            for (int k = 0; k < 12; k++) win[k] = sm->WTin[k][d];
            float bb = sm->b_in[d];
            #pragma unroll
            for (int r = 0; r < 18; r++) {
                int n = quad * 18 + r;
                float a = bb;
                const float4* xp = (const float4*)sm->xs[n];
                #pragma unroll
                for (int q = 0; q < 3; q++) {
                    float4 v = xp[q];
                    a += v.x * win[4*q] + v.y * win[4*q+1] + v.z * win[4*q+2] + v.w * win[4*q+3];
                }
                sm->h[n][d] = a;
            }
        }
        __syncthreads();

        gnn_layer(sm, tid, d, quad, sm->WT1rel, sm->WTd1, sm->b1v);
        gnn_layer(sm, tid, d, quad, sm->WT2rel, sm->WTd2, sm->b2v);

        // ---- heads: nodes 1..8, per-node [64 -> 2]; loc & softplus scale ----
        if (tid < GB * 8 * 2) {
            int o = tid & 1, j = (tid >> 1) & 7, g = tid >> 4;
            float a = sm->bh[j][o];
            const float4* hp = (const float4*)sm->h[g * NPG + j + 1];
            #pragma unroll
            for (int q = 0; q < 16; q++) {
                float4 v = hp[q];
                a += v.x * sm->Wh[j][4*q+0][o] + v.y * sm->Wh[j][4*q+1][o]
                   + v.z * sm->Wh[j][4*q+2][o] + v.w * sm->Wh[j][4*q+3][o];
            }
            long long gi = (g0 + g) * 8 + j;
            if (o == 0) {
                out[gi] = a;
            } else {
                float z = a + SOFTPLUS_BIAS;
                float sp = (z > 20.f) ? z : log1pf(__expf(z));
                out[(long long)B_GRAPHS * 8 + gi] = fmaxf(sp, 1e-4f);
            }
        }
    }
}

extern "C" void kernel_launch(void* const* d_in, const int* in_sizes, int n_in,
                              void* d_out, int out_size)
{
    (void)in_sizes; (void)n_in; (void)out_size;
    const float* x      = (const float*)d_in[0];
    // d_in[1] = edge_index: structurally known (dense 9-node graphs) -> unused
    const float* W_in   = (const float*)d_in[2];
    const float* b_in   = (const float*)d_in[3];
    const float* W1_rel = (const float*)d_in[4];
    const float* b1     = (const float*)d_in[5];
    const float* W1_root= (const float*)d_in[6];
    const float* W2_rel = (const float*)d_in[7];
    const float* b2     = (const float*)d_in[8];
    const float* W2_root= (const float*)d_in[9];
    const float* W_head = (const float*)d_in[10];
    const float* b_head = (const float*)d_in[11];
    float* out = (float*)d_out;

    const int smem = (int)sizeof(Smem);
    cudaFuncSetAttribute(gnn_kernel, cudaFuncAttributeMaxDynamicSharedMemorySize, smem);
    gnn_kernel<<<304, THREADS, smem>>>(x, W_in, b_in, W1_rel, b1, W1_root,
                                       W2_rel, b2, W2_root, W_head, b_head, out);
}

// round 3
// speedup vs baseline: 1.0221x; 1.0221x over previous
#include <cuda_runtime.h>
#include <math.h>

#define NPG 9
#define G 32                  // graphs per tile
#define NODES 288             // G*NPG
#define TPB 288               // 9 warps, 1 node per thread
#define HS 66                 // h row stride (floats); 66 mod 32 = 2 -> <=2-way conflicts
#define NTILES 2048           // 65536 / G
#define TOTOUT 524288         // 65536*8
#define SOFTPLUS_BIAS 0.54132485461291809f

// shared memory layout (float offsets)
#define OFF_WD1 0             // [64][64] W1_root - W1_rel, row-major [d][k]
#define OFF_WD2 4096
#define OFF_WR1 8192          // [64][64] W1_rel
#define OFF_WR2 12288
#define OFF_WIN 16384         // [64][12], col 11 zero
#define OFF_BIN 17152
#define OFF_B1  17216
#define OFF_B2  17280
#define OFF_BH  17344         // [16]
#define OFF_WHT 17360         // [16][64]  head weights, row (j*2+o), cols k
#define OFF_CS  18384         // [32][HS]  per-graph column sums
#define OFF_S   20496         // [32][HS]  S = b + colsum @ Wrel^T
#define OFF_H   22608         // [288][HS]
#define SMEM_FLOATS 41616     // 166,464 bytes

typedef unsigned long long u64;

__device__ __forceinline__ u64 ffma2(u64 a, u64 b, u64 c) {
    u64 d; asm("fma.rn.f32x2 %0,%1,%2,%3;" : "=l"(d) : "l"(a), "l"(b), "l"(c)); return d;
}
__device__ __forceinline__ u64 fadd2(u64 a, u64 b) {
    u64 d; asm("add.rn.f32x2 %0,%1,%2;" : "=l"(d) : "l"(a), "l"(b)); return d;
}
__device__ __forceinline__ float red2(u64 a) {
    float lo, hi; asm("mov.b64 {%0,%1},%2;" : "=f"(lo), "=f"(hi) : "l"(a)); return lo + hi;
}
__device__ __forceinline__ u64 pack2(float lo, float hi) {
    u64 v; asm("mov.b64 %0,{%1,%2};" : "=l"(v) : "f"(lo), "f"(hi)); return v;
}
__device__ __forceinline__ u64 lds64(unsigned a) {
    u64 v; asm volatile("ld.shared.u64 %0,[%1];" : "=l"(v) : "r"(a)); return v;
}
__device__ __forceinline__ void lds128(unsigned a, u64 &x, u64 &y) {
    asm volatile("ld.shared.v2.u64 {%0,%1},[%2];" : "=l"(x), "=l"(y) : "r"(a));
}
__device__ __forceinline__ void sts64(unsigned a, u64 v) {
    asm volatile("st.shared.u64 [%0],%1;" :: "r"(a), "l"(v));
}
__device__ __forceinline__ float tanh_fast(float x) {
    float y; asm("tanh.approx.f32 %0,%1;" : "=f"(y) : "f"(x)); return y;
}

// One GraphConv layer: colsum -> S = b + colsum@Wrel^T -> h' = tanh(S + h@Wd^T)
__device__ __forceinline__ void gnn_layer(float* sm, unsigned sb, int t, int gq,
                                          int wroff, int boff, int wdoff)
{
    // ---- colsum[g][k] = sum over 9 nodes (256 threads: 32 g x 8 k-chunks) ----
    if (t < 256) {
        const int g = t >> 3, kq = t & 7;
        unsigned a = sb + (unsigned)(OFF_H + g * 9 * HS + kq * 8) * 4u;
        u64 s0 = lds64(a), s1 = lds64(a + 8), s2 = lds64(a + 16), s3 = lds64(a + 24);
        #pragma unroll
        for (int n = 1; n < 9; n++) {
            unsigned r = a + (unsigned)(n * HS) * 4u;
            s0 = fadd2(s0, lds64(r));
            s1 = fadd2(s1, lds64(r + 8));
            s2 = fadd2(s2, lds64(r + 16));
            s3 = fadd2(s3, lds64(r + 24));
        }
        unsigned o = sb + (unsigned)(OFF_CS + g * HS + kq * 8) * 4u;
        sts64(o, s0); sts64(o + 8, s1); sts64(o + 16, s2); sts64(o + 24, s3);
    }
    __syncthreads();

    // ---- S[g][d] = b[d] + colsum[g] . Wrel[d]  (256 threads: 32 g x 8 d-sets) ----
    if (t < 256) {
        const int g = t & 31, ds = t >> 5;
        u64 c[32];
        unsigned cr = sb + (unsigned)(OFF_CS + g * HS) * 4u;
        #pragma unroll
        for (int q = 0; q < 32; q++) c[q] = lds64(cr + q * 8u);
        const float* bias = sm + boff;
        float* Srow = sm + OFF_S + g * HS;
        #pragma unroll 2
        for (int i = 0; i < 8; i++) {
            const int d = ds * 8 + i;
            unsigned wr = sb + (unsigned)(wroff + d * 64) * 4u;
            u64 a0 = 0, a1 = 0, a2 = 0, a3 = 0;
            #pragma unroll
            for (int q = 0; q < 8; q++) {
                u64 w0, w1, w2, w3;
                lds128(wr + q * 32u, w0, w1);
                lds128(wr + q * 32u + 16u, w2, w3);
                a0 = ffma2(w0, c[4*q],   a0);
                a1 = ffma2(w1, c[4*q+1], a1);
                a2 = ffma2(w2, c[4*q+2], a2);
                a3 = ffma2(w3, c[4*q+3], a3);
            }
            Srow[d] = bias[d] + red2(fadd2(fadd2(a0, a1), fadd2(a2, a3)));
        }
    }
    __syncthreads();

    // ---- per-node transform: h' = tanh(S[g] + h @ Wd^T), h register-resident ----
    {
        u64 h[32];
        unsigned hr = sb + (unsigned)(OFF_H + t * HS) * 4u;
        #pragma unroll
        for (int q = 0; q < 32; q++) h[q] = lds64(hr + q * 8u);
        const float* Srow = sm + OFF_S + gq * HS;
        unsigned wb = sb + (unsigned)wdoff * 4u;
        #pragma unroll 2
        for (int dp = 0; dp < 32; dp++) {
            const int d = dp * 2;
            unsigned w0r = wb + (unsigned)d * 256u;
            unsigned w1r = w0r + 256u;
            u64 a0 = 0, a1 = 0, a2 = 0, a3 = 0;
            u64 b0 = 0, b1 = 0, b2 = 0, b3 = 0;
            #pragma unroll
            for (int q = 0; q < 8; q++) {
                u64 w0, w1, w2, w3, v0, v1, v2, v3;
                lds128(w0r + q * 32u, w0, w1);
                lds128(w0r + q * 32u + 16u, w2, w3);
                lds128(w1r + q * 32u, v0, v1);
                lds128(w1r + q * 32u + 16u, v2, v3);
                a0 = ffma2(w0, h[4*q],   a0);
                a1 = ffma2(w1, h[4*q+1], a1);
                a2 = ffma2(w2, h[4*q+2], a2);
                a3 = ffma2(w3, h[4*q+3], a3);
                b0 = ffma2(v0, h[4*q],   b0);
                b1 = ffma2(v1, h[4*q+1], b1);
                b2 = ffma2(v2, h[4*q+2], b2);
                b3 = ffma2(v3, h[4*q+3], b3);
            }
            float va = tanh_fast(red2(fadd2(fadd2(a0, a1), fadd2(a2, a3))) + Srow[d]);
            float vb = tanh_fast(red2(fadd2(fadd2(b0, b1), fadd2(b2, b3))) + Srow[d + 1]);
            sts64(hr + (unsigned)d * 4u, pack2(va, vb));
        }
    }
    __syncthreads();
}

__global__ __launch_bounds__(TPB, 1)
void gnn_kernel(const float* __restrict__ x,
                const float* __restrict__ gWin,  const float* __restrict__ gbin,
                const float* __restrict__ gW1rel, const float* __restrict__ gb1,
                const float* __restrict__ gW1root,
                const float* __restrict__ gW2rel, const float* __restrict__ gb2,
                const float* __restrict__ gW2root,
                const float* __restrict__ gWhead, const float* __restrict__ gbhead,
                float* __restrict__ out)
{
    extern __shared__ float sm[];
    const unsigned sb = (unsigned)__cvta_generic_to_shared(sm);
    const int t = threadIdx.x;

    // ---- one-time weight staging ----
    for (int i = t; i < 4096; i += TPB) {
        float r1 = gW1rel[i];
        sm[OFF_WR1 + i] = r1;
        sm[OFF_WD1 + i] = gW1root[i] - r1;
        float r2 = gW2rel[i];
        sm[OFF_WR2 + i] = r2;
        sm[OFF_WD2 + i] = gW2root[i] - r2;
    }
    for (int i = t; i < 768; i += TPB) {
        int d = i / 12, k = i - d * 12;
        sm[OFF_WIN + i] = (k < 11) ? gWin[d * 11 + k] : 0.f;
    }
    for (int i = t; i < 1024; i += TPB) {
        // gWhead layout (8,64,2): i = j*128 + k*2 + o  ->  WhT[(j*2+o)*64 + k]
        int j = i >> 7, r = i & 127, k = r >> 1, o = r & 1;
        sm[OFF_WHT + (j * 2 + o) * 64 + k] = gWhead[i];
    }
    if (t < 64) { sm[OFF_BIN + t] = gbin[t]; sm[OFF_B1 + t] = gb1[t]; sm[OFF_B2 + t] = gb2[t]; }
    if (t < 16) sm[OFF_BH + t] = gbhead[t];
    __syncthreads();

    const int gq = t / 9;          // my node's local graph
    const int wj = t >> 5;         // head phase: warp id = node j
    const int lg = t & 31;         // head phase: graph

    for (int tile = blockIdx.x; tile < NTILES; tile += gridDim.x) {
        // ---- prefetch my node's x into registers (global, overlaps barrier) ----
        const float* xp = x + (tile * NODES + t) * 11;
        float xr[12];
        #pragma unroll
        for (int k = 0; k < 11; k++) xr[k] = xp[k];
        xr[11] = 0.f;
        u64 xv[6];
        #pragma unroll
        for (int q = 0; q < 6; q++) xv[q] = pack2(xr[2*q], xr[2*q+1]);

        __syncthreads();   // previous tile's heads finished reading h

        // ---- input layer: h = x @ Win^T + b_in ----
        {
            unsigned hr = sb + (unsigned)(OFF_H + t * HS) * 4u;
            const float* bin = sm + OFF_BIN;
            #pragma unroll 4
            for (int dp = 0; dp < 32; dp++) {
                const int d = dp * 2;
                unsigned w0r = sb + (unsigned)(OFF_WIN + d * 12) * 4u;
                unsigned w1r = w0r + 48u;
                u64 a0 = 0, a1 = 0, b0 = 0, b1 = 0;
                #pragma unroll
                for (int q = 0; q < 3; q++) {
                    u64 w0, w1, v0, v1;
                    lds128(w0r + q * 16u, w0, w1);
                    lds128(w1r + q * 16u, v0, v1);
                    a0 = ffma2(w0, xv[2*q],   a0);
                    a1 = ffma2(w1, xv[2*q+1], a1);
                    b0 = ffma2(v0, xv[2*q],   b0);
                    b1 = ffma2(v1, xv[2*q+1], b1);
                }
                float va = red2(fadd2(a0, a1)) + bin[d];
                float vb = red2(fadd2(b0, b1)) + bin[d + 1];
                sts64(hr + (unsigned)d * 4u, pack2(va, vb));
            }
        }
        __syncthreads();

        gnn_layer(sm, sb, t, gq, OFF_WR1, OFF_B1, OFF_WD1);
        gnn_layer(sm, sb, t, gq, OFF_WR2, OFF_B2, OFF_WD2);

        // ---- heads: warp j handles node j+1 of 32 graphs (both outputs) ----
        if (t < 256) {
            u64 h[32];
            unsigned hr = sb + (unsigned)(OFF_H + (lg * 9 + wj + 1) * HS) * 4u;
            #pragma unroll
            for (int q = 0; q < 32; q++) h[q] = lds64(hr + q * 8u);
            float res[2];
            #pragma unroll
            for (int o = 0; o < 2; o++) {
                unsigned wr = sb + (unsigned)(OFF_WHT + (wj * 2 + o) * 64) * 4u;
                u64 a0 = 0, a1 = 0, a2 = 0, a3 = 0;
                #pragma unroll
                for (int q = 0; q < 8; q++) {
                    u64 w0, w1, w2, w3;
                    lds128(wr + q * 32u, w0, w1);
                    lds128(wr + q * 32u + 16u, w2, w3);
                    a0 = ffma2(w0, h[4*q],   a0);
                    a1 = ffma2(w1, h[4*q+1], a1);
                    a2 = ffma2(w2, h[4*q+2], a2);
                    a3 = ffma2(w3, h[4*q+3], a3);
                }
                res[o] = sm[OFF_BH + wj * 2 + o]
                       + red2(fadd2(fadd2(a0, a1), fadd2(a2, a3)));
            }
            const long long gi = (long long)(tile * G + lg) * 8 + wj;
            out[gi] = res[0];
            float z = res[1] + SOFTPLUS_BIAS;
            float sp = (z > 20.f) ? z : log1pf(__expf(z));
            out[TOTOUT + gi] = fmaxf(sp, 1e-4f);
        }
    }
}

extern "C" void kernel_launch(void* const* d_in, const int* in_sizes, int n_in,
                              void* d_out, int out_size)
{
    (void)in_sizes; (void)n_in; (void)out_size;
    const float* x      = (const float*)d_in[0];
    // d_in[1] = edge_index: dense 9-node graphs, structurally known -> unused
    const float* W_in   = (const float*)d_in[2];
    const float* b_in   = (const float*)d_in[3];
    const float* W1_rel = (const float*)d_in[4];
    const float* b1     = (const float*)d_in[5];
    const float* W1_root= (const float*)d_in[6];
    const float* W2_rel = (const float*)d_in[7];
    const float* b2     = (const float*)d_in[8];
    const float* W2_root= (const float*)d_in[9];
    const float* W_head = (const float*)d_in[10];
    const float* b_head = (const float*)d_in[11];
    float* out = (float*)d_out;

    int nsm = 148;
    cudaDeviceGetAttribute(&nsm, cudaDevAttrMultiProcessorCount, 0);

    const int smem = SMEM_FLOATS * 4;
    cudaFuncSetAttribute(gnn_kernel, cudaFuncAttributeMaxDynamicSharedMemorySize, smem);
    gnn_kernel<<<nsm, TPB, smem>>>(x, W_in, b_in, W1_rel, b1, W1_root,
                                   W2_rel, b2, W2_root, W_head, b_head, out);
}

// round 4
// speedup vs baseline: 1.1183x; 1.0941x over previous
#include <cuda_runtime.h>
#include <math.h>

#define NPG 9
#define G 32                  // graphs per tile
#define NODES 288
#define TPB 288               // 9 warps; transform: warp w -> nodes [32w,32w+32), lane owns d=l, l+32
#define HS 68                 // h row stride (floats): 16B-aligned rows, 4-way worst conflicts
#define WS 68                 // weight row stride
#define NTILES 2048           // 65536 / G
#define TOTOUT 524288         // 65536*8
#define SOFTPLUS_BIAS 0.54132485461291809f

// shared layout (float offsets)
#define OFF_WD1 0             // [64][68]  W1_root - W1_rel, rows [d][k]
#define OFF_WD2 4352
#define OFF_WR1 8704          // [64][68]  W1_rel
#define OFF_WR2 13056
#define OFF_WIN 17408         // [64][12]  input weights (col 11 zero)
#define OFF_WHT 18176         // [16][64]  head weights, row j*2+o
#define OFF_BIN 19200
#define OFF_B1  19264
#define OFF_B2  19328
#define OFF_BH  19392         // [16]
#define OFF_XS  19408         // [288][12] x tile (col 11 zero)
#define OFF_CS  22864         // [32][68]  per-graph column sums
#define OFF_S   25040         // [32][68]  S = b + colsum @ Wrel^T
#define OFF_H   27216         // [288][68]
#define SMEM_FLOATS 46800     // 187,200 bytes

typedef unsigned long long u64;

__device__ __forceinline__ u64 ffma2(u64 a, u64 b, u64 c) {
    u64 d; asm("fma.rn.f32x2 %0,%1,%2,%3;" : "=l"(d) : "l"(a), "l"(b), "l"(c)); return d;
}
__device__ __forceinline__ u64 fadd2(u64 a, u64 b) {
    u64 d; asm("add.rn.f32x2 %0,%1,%2;" : "=l"(d) : "l"(a), "l"(b)); return d;
}
__device__ __forceinline__ float red2(u64 a) {
    float lo, hi; asm("mov.b64 {%0,%1},%2;" : "=f"(lo), "=f"(hi) : "l"(a)); return lo + hi;
}
__device__ __forceinline__ u64 lds64(unsigned a) {
    u64 v; asm volatile("ld.shared.u64 %0,[%1];" : "=l"(v) : "r"(a)); return v;
}
__device__ __forceinline__ void lds128(unsigned a, u64 &x, u64 &y) {
    asm volatile("ld.shared.v2.u64 {%0,%1},[%2];" : "=l"(x), "=l"(y) : "r"(a));
}
__device__ __forceinline__ float lds32(unsigned a) {
    float v; asm volatile("ld.shared.f32 %0,[%1];" : "=f"(v) : "r"(a)); return v;
}
__device__ __forceinline__ void sts32(unsigned a, float v) {
    asm volatile("st.shared.f32 [%0],%1;" :: "r"(a), "f"(v));
}
__device__ __forceinline__ void sts64(unsigned a, u64 v) {
    asm volatile("st.shared.u64 [%0],%1;" :: "r"(a), "l"(v));
}
__device__ __forceinline__ float tanh_fast(float x) {
    float y; asm("tanh.approx.f32 %0,%1;" : "=f"(y) : "f"(x)); return y;
}

// colsum + S phases (weight-broadcast, 256 threads), then register-stationary transform
__device__ __forceinline__ void gnn_layer(unsigned sb, int t, int lane, int w,
                                          int wroff, int boff, int wdoff)
{
    // ---- colsum[g][k] = sum over 9 nodes ----
    if (t < 256) {
        const int g = t >> 3, kq = t & 7;
        const unsigned a = sb + (unsigned)(OFF_H + g * 9 * HS + kq * 8) * 4u;
        u64 s0 = lds64(a), s1 = lds64(a + 8), s2 = lds64(a + 16), s3 = lds64(a + 24);
        #pragma unroll
        for (int n = 1; n < 9; n++) {
            const unsigned r = a + (unsigned)(n * HS) * 4u;
            s0 = fadd2(s0, lds64(r));
            s1 = fadd2(s1, lds64(r + 8));
            s2 = fadd2(s2, lds64(r + 16));
            s3 = fadd2(s3, lds64(r + 24));
        }
        const unsigned o = sb + (unsigned)(OFF_CS + g * HS + kq * 8) * 4u;
        sts64(o, s0); sts64(o + 8, s1); sts64(o + 16, s2); sts64(o + 24, s3);
    }
    __syncthreads();

    // ---- S[g][d] = b[d] + CS[g] . Wrel[d]   (warps 0..7: warp=d-set, lane=g) ----
    if (t < 256) {
        const int g = lane;
        u64 c[32];
        const unsigned cr = sb + (unsigned)(OFF_CS + g * HS) * 4u;
        #pragma unroll
        for (int q = 0; q < 32; q++) c[q] = lds64(cr + q * 8u);
        #pragma unroll 2
        for (int i = 0; i < 8; i++) {
            const int d = w * 8 + i;
            const unsigned wr = sb + (unsigned)(wroff + d * WS) * 4u;
            u64 a0 = 0, a1 = 0, a2 = 0, a3 = 0;
            #pragma unroll
            for (int q = 0; q < 8; q++) {
                u64 w0, w1, w2, w3;
                lds128(wr + q * 32u, w0, w1);
                lds128(wr + q * 32u + 16u, w2, w3);
                a0 = ffma2(w0, c[4*q],   a0);
                a1 = ffma2(w1, c[4*q+1], a1);
                a2 = ffma2(w2, c[4*q+2], a2);
                a3 = ffma2(w3, c[4*q+3], a3);
            }
            const float sv = lds32(sb + (unsigned)(boff + d) * 4u)
                           + red2(fadd2(fadd2(a0, a1), fadd2(a2, a3)));
            sts32(sb + (unsigned)(OFF_S + g * HS + d) * 4u, sv);
        }
    }
    __syncthreads();

    // ---- transform: h'[n] = tanh(S[g(n)] + h[n] @ Wd^T) ----
    {
        // lane-stationary weights: rows d=lane and d=lane+32 (64 u64)
        u64 wa[32], wb[32];
        const unsigned wra = sb + (unsigned)(wdoff + lane * WS) * 4u;
        const unsigned wrb = sb + (unsigned)(wdoff + (lane + 32) * WS) * 4u;
        #pragma unroll
        for (int q = 0; q < 16; q++) lds128(wra + q * 16u, wa[2*q], wa[2*q+1]);
        #pragma unroll
        for (int q = 0; q < 16; q++) lds128(wrb + q * 16u, wb[2*q], wb[2*q+1]);

        const int n0 = w * 32;
        int g = (n0 * 7282) >> 16;            // n0/9 for n0<576
        int rem = n0 - g * 9;
        unsigned hr = sb + (unsigned)(OFF_H + n0 * HS) * 4u;
        const unsigned sA = sb + (unsigned)(OFF_S + lane) * 4u;

        #pragma unroll 2
        for (int n = 0; n < 32; n++) {
            u64 a0 = 0, a1 = 0, b0 = 0, b1 = 0;
            #pragma unroll
            for (int q = 0; q < 16; q++) {
                u64 h0, h1;
                lds128(hr + q * 16u, h0, h1);
                a0 = ffma2(wa[2*q],   h0, a0);
                a1 = ffma2(wa[2*q+1], h1, a1);
                b0 = ffma2(wb[2*q],   h0, b0);
                b1 = ffma2(wb[2*q+1], h1, b1);
            }
            const unsigned srow = sA + (unsigned)(g * HS) * 4u;
            const float s0 = lds32(srow);
            const float s1 = lds32(srow + 128u);
            const float va = tanh_fast(red2(fadd2(a0, a1)) + s0);
            const float vb = tanh_fast(red2(fadd2(b0, b1)) + s1);
            sts32(hr + (unsigned)lane * 4u, va);
            sts32(hr + (unsigned)(lane + 32) * 4u, vb);
            hr += HS * 4u;
            if (++rem == 9) { rem = 0; g++; }
        }
    }
    __syncthreads();
}

__global__ __launch_bounds__(TPB, 1)
void gnn_kernel(const float* __restrict__ x,
                const float* __restrict__ gWin,  const float* __restrict__ gbin,
                const float* __restrict__ gW1rel, const float* __restrict__ gb1,
                const float* __restrict__ gW1root,
                const float* __restrict__ gW2rel, const float* __restrict__ gb2,
                const float* __restrict__ gW2root,
                const float* __restrict__ gWhead, const float* __restrict__ gbhead,
                float* __restrict__ out)
{
    extern __shared__ float sm[];
    const unsigned sb = (unsigned)__cvta_generic_to_shared(sm);
    const int t = threadIdx.x;
    const int lane = t & 31, w = t >> 5;

    // ---- one-time staging ----
    for (int i = t; i < 4096; i += TPB) {
        const int d = i >> 6, k = i & 63;
        const float r1 = gW1rel[i];
        sm[OFF_WR1 + d * WS + k] = r1;
        sm[OFF_WD1 + d * WS + k] = gW1root[i] - r1;
        const float r2 = gW2rel[i];
        sm[OFF_WR2 + d * WS + k] = r2;
        sm[OFF_WD2 + d * WS + k] = gW2root[i] - r2;
    }
    for (int i = t; i < 768; i += TPB) {
        const int d = i / 12, k = i - d * 12;
        sm[OFF_WIN + i] = (k < 11) ? gWin[d * 11 + k] : 0.f;
    }
    for (int i = t; i < 1024; i += TPB) {
        const int j = i >> 7, r = i & 127, k = r >> 1, o = r & 1;
        sm[OFF_WHT + (j * 2 + o) * 64 + k] = gWhead[i];
    }
    if (t < 64) { sm[OFF_BIN + t] = gbin[t]; sm[OFF_B1 + t] = gb1[t]; sm[OFF_B2 + t] = gb2[t]; }
    if (t < 16) sm[OFF_BH + t] = gbhead[t];
    sm[OFF_XS + t * 12 + 11] = 0.f;   // x pad column, persists across tiles
    __syncthreads();

    for (int tile = blockIdx.x; tile < NTILES; tile += gridDim.x) {
        // ---- stage x coalesced ----
        const float* xg = x + (long long)tile * (NODES * 11);
        #pragma unroll
        for (int rr = 0; rr < 11; rr++) {
            const int i = t + rr * TPB;
            const int n = (i * 5958) >> 16;      // i/11 for i<3168
            sm[OFF_XS + n * 12 + (i - n * 11)] = xg[i];
        }
        __syncthreads();   // x staged + previous tile's heads done with h

        // ---- input layer: register-stationary weights, x broadcast ----
        {
            u64 wi[12];
            const unsigned wr0 = sb + (unsigned)(OFF_WIN + lane * 12) * 4u;
            const unsigned wr1 = sb + (unsigned)(OFF_WIN + (lane + 32) * 12) * 4u;
            #pragma unroll
            for (int q = 0; q < 3; q++) lds128(wr0 + q * 16u, wi[2*q],   wi[2*q+1]);
            #pragma unroll
            for (int q = 0; q < 3; q++) lds128(wr1 + q * 16u, wi[6+2*q], wi[6+2*q+1]);
            const float bi0 = sm[OFF_BIN + lane], bi1 = sm[OFF_BIN + lane + 32];

            unsigned xr = sb + (unsigned)(OFF_XS + w * 32 * 12) * 4u;
            unsigned hw = sb + (unsigned)(OFF_H + w * 32 * HS) * 4u;
            #pragma unroll 4
            for (int n = 0; n < 32; n++) {
                u64 a0 = 0, a1 = 0, b0 = 0, b1 = 0;
                #pragma unroll
                for (int q = 0; q < 3; q++) {
                    u64 x0, x1;
                    lds128(xr + q * 16u, x0, x1);
                    a0 = ffma2(wi[2*q],     x0, a0);
                    a1 = ffma2(wi[2*q+1],   x1, a1);
                    b0 = ffma2(wi[6+2*q],   x0, b0);
                    b1 = ffma2(wi[6+2*q+1], x1, b1);
                }
                sts32(hw + (unsigned)lane * 4u,        red2(fadd2(a0, a1)) + bi0);
                sts32(hw + (unsigned)(lane + 32) * 4u, red2(fadd2(b0, b1)) + bi1);
                xr += 48u;
                hw += HS * 4u;
            }
        }
        __syncthreads();

        gnn_layer(sb, t, lane, w, OFF_WR1, OFF_B1, OFF_WD1);
        gnn_layer(sb, t, lane, w, OFF_WR2, OFF_B2, OFF_WD2);

        // ---- heads: warp w = node j (0..7), lane = graph ----
        if (t < 256) {
            u64 h[32];
            const unsigned hr = sb + (unsigned)(OFF_H + (lane * 9 + w + 1) * HS) * 4u;
            #pragma unroll
            for (int q = 0; q < 32; q++) h[q] = lds64(hr + q * 8u);
            float res[2];
            #pragma unroll
            for (int o = 0; o < 2; o++) {
                const unsigned wr = sb + (unsigned)(OFF_WHT + (w * 2 + o) * 64) * 4u;
                u64 a0 = 0, a1 = 0, a2 = 0, a3 = 0;
                #pragma unroll
                for (int q = 0; q < 8; q++) {
                    u64 w0, w1, w2, w3;
                    lds128(wr + q * 32u, w0, w1);
                    lds128(wr + q * 32u + 16u, w2, w3);
                    a0 = ffma2(w0, h[4*q],   a0);
                    a1 = ffma2(w1, h[4*q+1], a1);
                    a2 = ffma2(w2, h[4*q+2], a2);
                    a3 = ffma2(w3, h[4*q+3], a3);
                }
                res[o] = sm[OFF_BH + w * 2 + o]
                       + red2(fadd2(fadd2(a0, a1), fadd2(a2, a3)));
            }
            const long long gi = (long long)(tile * G + lane) * 8 + w;
            out[gi] = res[0];
            const float z = res[1] + SOFTPLUS_BIAS;
            const float sp = (z > 20.f) ? z : log1pf(__expf(z));
            out[TOTOUT + gi] = fmaxf(sp, 1e-4f);
        }
    }
}

extern "C" void kernel_launch(void* const* d_in, const int* in_sizes, int n_in,
                              void* d_out, int out_size)
{
    (void)in_sizes; (void)n_in; (void)out_size;
    const float* x      = (const float*)d_in[0];
    // d_in[1] = edge_index: dense 9-node graphs, structurally known -> unused
    const float* W_in   = (const float*)d_in[2];
    const float* b_in   = (const float*)d_in[3];
    const float* W1_rel = (const float*)d_in[4];
    const float* b1     = (const float*)d_in[5];
    const float* W1_root= (const float*)d_in[6];
    const float* W2_rel = (const float*)d_in[7];
    const float* b2     = (const float*)d_in[8];
    const float* W2_root= (const float*)d_in[9];
    const float* W_head = (const float*)d_in[10];
    const float* b_head = (const float*)d_in[11];
    float* out = (float*)d_out;

    int nsm = 148;
    cudaDeviceGetAttribute(&nsm, cudaDevAttrMultiProcessorCount, 0);

    const int smem = SMEM_FLOATS * 4;
    cudaFuncSetAttribute(gnn_kernel, cudaFuncAttributeMaxDynamicSharedMemorySize, smem);
    gnn_kernel<<<nsm, TPB, smem>>>(x, W_in, b_in, W1_rel, b1, W1_root,
                                   W2_rel, b2, W2_root, W_head, b_head, out);
}

// round 5
// speedup vs baseline: 1.2818x; 1.1463x over previous
#include <cuda_runtime.h>
#include <math.h>

#define NPG 9
#define G 32                  // graphs per tile
#define NODES 288
#define TPB 384               // 12 warps; transform: warp w -> 24 nodes, lane owns d=l, l+32
#define NPW 24                // nodes per warp in transform
#define HS 68                 // h row stride
#define CSS 66                // colsum row stride (2-way worst)
#define SS 65                 // S row stride (conflict-free scalar access)
#define NTILES 2048           // 65536 / G
#define TOTOUT 524288         // 65536*8
#define SOFTPLUS_BIAS 0.54132485461291809f

// shared layout (float offsets)
#define OFF_WD1 0             // [64][64] swizzled: W1_root - W1_rel
#define OFF_WD2 4096
#define OFF_WR1 8192          // [64][64] linear (uniform reads only)
#define OFF_WR2 12288
#define OFF_WIN 16384         // [64][12]
#define OFF_WHT 17152         // [16][64]
#define OFF_BIN 18176
#define OFF_B1  18240
#define OFF_B2  18304
#define OFF_BH  18368         // [16]
#define OFF_XS  18384         // [288][12]
#define OFF_CS  21840         // [32][66]
#define OFF_S   23952         // [32][65]
#define OFF_H   26032         // [288][68]
#define SMEM_FLOATS 45616     // 182,464 bytes

typedef unsigned long long u64;

__device__ __forceinline__ u64 ffma2(u64 a, u64 b, u64 c) {
    u64 d; asm("fma.rn.f32x2 %0,%1,%2,%3;" : "=l"(d) : "l"(a), "l"(b), "l"(c)); return d;
}
__device__ __forceinline__ u64 fadd2(u64 a, u64 b) {
    u64 d; asm("add.rn.f32x2 %0,%1,%2;" : "=l"(d) : "l"(a), "l"(b)); return d;
}
__device__ __forceinline__ float red2(u64 a) {
    float lo, hi; asm("mov.b64 {%0,%1},%2;" : "=f"(lo), "=f"(hi) : "l"(a)); return lo + hi;
}
__device__ __forceinline__ u64 lds64(unsigned a) {
    u64 v; asm volatile("ld.shared.u64 %0,[%1];" : "=l"(v) : "r"(a)); return v;
}
__device__ __forceinline__ void lds128(unsigned a, u64 &x, u64 &y) {
    asm volatile("ld.shared.v2.u64 {%0,%1},[%2];" : "=l"(x), "=l"(y) : "r"(a));
}
__device__ __forceinline__ float lds32(unsigned a) {
    float v; asm volatile("ld.shared.f32 %0,[%1];" : "=f"(v) : "r"(a)); return v;
}
__device__ __forceinline__ void sts32(unsigned a, float v) {
    asm volatile("st.shared.f32 [%0],%1;" :: "r"(a), "f"(v));
}
__device__ __forceinline__ void sts64(unsigned a, u64 v) {
    asm volatile("st.shared.u64 [%0],%1;" :: "r"(a), "l"(v));
}
__device__ __forceinline__ float tanh_fast(float x) {
    float y; asm("tanh.approx.f32 %0,%1;" : "=f"(y) : "f"(x)); return y;
}

// swizzled word offset for Wd arrays: row r, float k. 16B chunks rotated by (r&7)
__device__ __forceinline__ int wd_off(int r, int k) {
    const int c = k >> 2, j = k & 3;
    const int hc = c >> 3, c8 = c & 7;
    return r * 64 + hc * 32 + (((c8 + r) & 7) << 2) + j;
}

// preload one swizzled row into 32 u64 regs (16 conflict-free lds128)
__device__ __forceinline__ void load_row_sw(unsigned sb, int wdoff, int r, u64* wreg) {
    #pragma unroll
    for (int c = 0; c < 16; c++) {
        const int hc = c >> 3, c8 = c & 7;
        const unsigned a = sb + (unsigned)(wdoff + r * 64 + hc * 32 + (((c8 + r) & 7) << 2)) * 4u;
        lds128(a, wreg[2*c], wreg[2*c+1]);
    }
}

__device__ __forceinline__ void gnn_layer(unsigned sb, int t, int lane, int w,
                                          int wroff, int boff, int wdoff)
{
    // ---- colsum[g][k] = sum over 9 nodes (256 threads: 32 g x 8 k-chunks) ----
    if (t < 256) {
        const int g = t >> 3, kq = t & 7;
        const unsigned a = sb + (unsigned)(OFF_H + g * 9 * HS + kq * 8) * 4u;
        u64 s0 = lds64(a), s1 = lds64(a + 8), s2 = lds64(a + 16), s3 = lds64(a + 24);
        #pragma unroll
        for (int n = 1; n < 9; n++) {
            const unsigned r = a + (unsigned)(n * HS) * 4u;
            s0 = fadd2(s0, lds64(r));
            s1 = fadd2(s1, lds64(r + 8));
            s2 = fadd2(s2, lds64(r + 16));
            s3 = fadd2(s3, lds64(r + 24));
        }
        const unsigned o = sb + (unsigned)(OFF_CS + g * CSS + kq * 8) * 4u;
        sts64(o, s0); sts64(o + 8, s1); sts64(o + 16, s2); sts64(o + 24, s3);
    }
    __syncthreads();

    // ---- S[g][d] = b[d] + CS[g] . Wrel[d]  (warps 0..7: warp=d-set, lane=g) ----
    if (t < 256) {
        const int g = lane;
        u64 c[32];
        const unsigned cr = sb + (unsigned)(OFF_CS + g * CSS) * 4u;
        #pragma unroll
        for (int q = 0; q < 32; q++) c[q] = lds64(cr + q * 8u);
        #pragma unroll 2
        for (int i = 0; i < 8; i++) {
            const int d = w * 8 + i;
            const unsigned wr = sb + (unsigned)(wroff + d * 64) * 4u;
            u64 a0 = 0, a1 = 0, a2 = 0, a3 = 0;
            #pragma unroll
            for (int q = 0; q < 8; q++) {
                u64 w0, w1, w2, w3;
                lds128(wr + q * 32u, w0, w1);
                lds128(wr + q * 32u + 16u, w2, w3);
                a0 = ffma2(w0, c[4*q],   a0);
                a1 = ffma2(w1, c[4*q+1], a1);
                a2 = ffma2(w2, c[4*q+2], a2);
                a3 = ffma2(w3, c[4*q+3], a3);
            }
            const float sv = lds32(sb + (unsigned)(boff + d) * 4u)
                           + red2(fadd2(fadd2(a0, a1), fadd2(a2, a3)));
            sts32(sb + (unsigned)(OFF_S + g * SS + d) * 4u, sv);
        }
    }
    __syncthreads();

    // ---- transform: h'[n] = tanh(S[g(n)] + h[n] @ Wd^T), weights lane-stationary ----
    {
        u64 wa[32], wb[32];
        load_row_sw(sb, wdoff, lane, wa);
        load_row_sw(sb, wdoff, lane + 32, wb);

        const int n0 = w * NPW;
        int g = (n0 * 7282) >> 16;            // n0/9 for n0<576
        int rem = n0 - g * 9;
        unsigned hr = sb + (unsigned)(OFF_H + n0 * HS) * 4u;

        #pragma unroll 2
        for (int n = 0; n < NPW; n++) {
            u64 a0 = 0, a1 = 0, b0 = 0, b1 = 0;
            #pragma unroll
            for (int q = 0; q < 16; q++) {
                u64 h0, h1;
                lds128(hr + q * 16u, h0, h1);
                a0 = ffma2(wa[2*q],   h0, a0);
                a1 = ffma2(wa[2*q+1], h1, a1);
                b0 = ffma2(wb[2*q],   h0, b0);
                b1 = ffma2(wb[2*q+1], h1, b1);
            }
            const unsigned srow = sb + (unsigned)(OFF_S + g * SS + lane) * 4u;
            const float s0 = lds32(srow);
            const float s1 = lds32(srow + 128u);
            const float va = tanh_fast(red2(fadd2(a0, a1)) + s0);
            const float vb = tanh_fast(red2(fadd2(b0, b1)) + s1);
            sts32(hr + (unsigned)lane * 4u, va);
            sts32(hr + (unsigned)(lane + 32) * 4u, vb);
            hr += HS * 4u;
            if (++rem == 9) { rem = 0; g++; }
        }
    }
    __syncthreads();
}

__global__ __launch_bounds__(TPB, 1)
void gnn_kernel(const float* __restrict__ x,
                const float* __restrict__ gWin,  const float* __restrict__ gbin,
                const float* __restrict__ gW1rel, const float* __restrict__ gb1,
                const float* __restrict__ gW1root,
                const float* __restrict__ gW2rel, const float* __restrict__ gb2,
                const float* __restrict__ gW2root,
                const float* __restrict__ gWhead, const float* __restrict__ gbhead,
                float* __restrict__ out)
{
    extern __shared__ float sm[];
    const unsigned sb = (unsigned)__cvta_generic_to_shared(sm);
    const int t = threadIdx.x;
    const int lane = t & 31, w = t >> 5;

    // ---- one-time staging ----
    for (int i = t; i < 4096; i += TPB) {
        const int d = i >> 6, k = i & 63;
        const int so = wd_off(d, k);
        const float r1 = gW1rel[i];
        sm[OFF_WR1 + i]  = r1;
        sm[OFF_WD1 + so] = gW1root[i] - r1;
        const float r2 = gW2rel[i];
        sm[OFF_WR2 + i]  = r2;
        sm[OFF_WD2 + so] = gW2root[i] - r2;
    }
    for (int i = t; i < 768; i += TPB) {
        const int d = i / 12, k = i - d * 12;
        sm[OFF_WIN + i] = (k < 11) ? gWin[d * 11 + k] : 0.f;
    }
    for (int i = t; i < 1024; i += TPB) {
        const int j = i >> 7, r = i & 127, k = r >> 1, o = r & 1;
        sm[OFF_WHT + (j * 2 + o) * 64 + k] = gWhead[i];
    }
    if (t < 64) { sm[OFF_BIN + t] = gbin[t]; sm[OFF_B1 + t] = gb1[t]; sm[OFF_B2 + t] = gb2[t]; }
    if (t < 16) sm[OFF_BH + t] = gbhead[t];
    if (t < 288) sm[OFF_XS + t * 12 + 11] = 0.f;   // x pad column, persists
    __syncthreads();

    for (int tile = blockIdx.x; tile < NTILES; tile += gridDim.x) {
        // ---- stage x coalesced ----
        const float* xg = x + (long long)tile * (NODES * 11);
        for (int i = t; i < NODES * 11; i += TPB) {
            const int n = (i * 5958) >> 16;      // i/11 for i<3168
            sm[OFF_XS + n * 12 + (i - n * 11)] = xg[i];
        }
        __syncthreads();

        // ---- input layer: register-stationary weights, x broadcast ----
        {
            u64 wi[12];
            const unsigned wr0 = sb + (unsigned)(OFF_WIN + lane * 12) * 4u;
            const unsigned wr1 = sb + (unsigned)(OFF_WIN + (lane + 32) * 12) * 4u;
            #pragma unroll
            for (int q = 0; q < 3; q++) lds128(wr0 + q * 16u, wi[2*q],   wi[2*q+1]);
            #pragma unroll
            for (int q = 0; q < 3; q++) lds128(wr1 + q * 16u, wi[6+2*q], wi[6+2*q+1]);
            const float bi0 = sm[OFF_BIN + lane], bi1 = sm[OFF_BIN + lane + 32];

            unsigned xr = sb + (unsigned)(OFF_XS + w * NPW * 12) * 4u;
            unsigned hw = sb + (unsigned)(OFF_H + w * NPW * HS) * 4u;
            #pragma unroll 4
            for (int n = 0; n < NPW; n++) {
                u64 a0 = 0, a1 = 0, b0 = 0, b1 = 0;
                #pragma unroll
                for (int q = 0; q < 3; q++) {
                    u64 x0, x1;
                    lds128(xr + q * 16u, x0, x1);
                    a0 = ffma2(wi[2*q],     x0, a0);
                    a1 = ffma2(wi[2*q+1],   x1, a1);
                    b0 = ffma2(wi[6+2*q],   x0, b0);
                    b1 = ffma2(wi[6+2*q+1], x1, b1);
                }
                sts32(hw + (unsigned)lane * 4u,        red2(fadd2(a0, a1)) + bi0);
                sts32(hw + (unsigned)(lane + 32) * 4u, red2(fadd2(b0, b1)) + bi1);
                xr += 48u;
                hw += HS * 4u;
            }
        }
        __syncthreads();

        gnn_layer(sb, t, lane, w, OFF_WR1, OFF_B1, OFF_WD1);
        gnn_layer(sb, t, lane, w, OFF_WR2, OFF_B2, OFF_WD2);

        // ---- heads: warp w = node j (0..7), lane = graph ----
        if (t < 256) {
            u64 h[32];
            const unsigned hr = sb + (unsigned)(OFF_H + (lane * 9 + w + 1) * HS) * 4u;
            #pragma unroll
            for (int q = 0; q < 32; q++) h[q] = lds64(hr + q * 8u);
            float res[2];
            #pragma unroll
            for (int o = 0; o < 2; o++) {
                const unsigned wr = sb + (unsigned)(OFF_WHT + (w * 2 + o) * 64) * 4u;
                u64 a0 = 0, a1 = 0, a2 = 0, a3 = 0;
                #pragma unroll
                for (int q = 0; q < 8; q++) {
                    u64 w0, w1, w2, w3;
                    lds128(wr + q * 32u, w0, w1);
                    lds128(wr + q * 32u + 16u, w2, w3);
                    a0 = ffma2(w0, h[4*q],   a0);
                    a1 = ffma2(w1, h[4*q+1], a1);
                    a2 = ffma2(w2, h[4*q+2], a2);
                    a3 = ffma2(w3, h[4*q+3], a3);
                }
                res[o] = sm[OFF_BH + w * 2 + o]
                       + red2(fadd2(fadd2(a0, a1), fadd2(a2, a3)));
            }
            const long long gi = (long long)(tile * G + lane) * 8 + w;
            out[gi] = res[0];
            const float z = res[1] + SOFTPLUS_BIAS;
            const float sp = (z > 20.f) ? z : log1pf(__expf(z));
            out[TOTOUT + gi] = fmaxf(sp, 1e-4f);
        }
    }
}

extern "C" void kernel_launch(void* const* d_in, const int* in_sizes, int n_in,
                              void* d_out, int out_size)
{
    (void)in_sizes; (void)n_in; (void)out_size;
    const float* x      = (const float*)d_in[0];
    // d_in[1] = edge_index: dense 9-node graphs, structurally known -> unused
    const float* W_in   = (const float*)d_in[2];
    const float* b_in   = (const float*)d_in[3];
    const float* W1_rel = (const float*)d_in[4];
    const float* b1     = (const float*)d_in[5];
    const float* W1_root= (const float*)d_in[6];
    const float* W2_rel = (const float*)d_in[7];
    const float* b2     = (const float*)d_in[8];
    const float* W2_root= (const float*)d_in[9];
    const float* W_head = (const float*)d_in[10];
    const float* b_head = (const float*)d_in[11];
    float* out = (float*)d_out;

    int nsm = 148;
    cudaDeviceGetAttribute(&nsm, cudaDevAttrMultiProcessorCount, 0);

    const int smem = SMEM_FLOATS * 4;
    cudaFuncSetAttribute(gnn_kernel, cudaFuncAttributeMaxDynamicSharedMemorySize, smem);
    gnn_kernel<<<nsm, TPB, smem>>>(x, W_in, b_in, W1_rel, b1, W1_root,
                                   W2_rel, b2, W2_root, W_head, b_head, out);
}

// round 6
// speedup vs baseline: 1.3135x; 1.0247x over previous
#include <cuda_runtime.h>
#include <math.h>

#define NPG 9
#define G 32                  // graphs per tile
#define NODES 288
#define TPB 384               // 12 warps; transform: warp w -> 24 nodes, lane owns d=l, l+32
#define NPW 24                // nodes per warp in transform
#define HS 68                 // h row stride (16B-aligned rows)
#define CSS 66                // colsum row stride
#define SS 65                 // S row stride (conflict-free scalar access)
#define NTILES 2048           // 65536 / G
#define TOTOUT 524288         // 65536*8
#define SOFTPLUS_BIAS 0.54132485461291809f

// shared layout (float offsets)
#define OFF_WD1 0             // [64][64] swizzled: W1_root - W1_rel
#define OFF_WD2 4096
#define OFF_WR1 8192          // [64][64] linear (uniform reads only)
#define OFF_WR2 12288
#define OFF_WIN 16384         // [64][12]
#define OFF_WHT 17152         // [16][64]
#define OFF_BIN 18176
#define OFF_B1  18240
#define OFF_B2  18304
#define OFF_BH  18368         // [16]
#define OFF_XS  18384         // [288][12]
#define OFF_CS  21840         // [32][66]
#define OFF_S   23952         // [32][65]
#define OFF_H   26032         // [288][68]
#define SMEM_FLOATS 45616     // 182,464 bytes

typedef unsigned long long u64;

__device__ __forceinline__ u64 ffma2(u64 a, u64 b, u64 c) {
    u64 d; asm("fma.rn.f32x2 %0,%1,%2,%3;" : "=l"(d) : "l"(a), "l"(b), "l"(c)); return d;
}
__device__ __forceinline__ u64 fadd2(u64 a, u64 b) {
    u64 d; asm("add.rn.f32x2 %0,%1,%2;" : "=l"(d) : "l"(a), "l"(b)); return d;
}
__device__ __forceinline__ float red2(u64 a) {
    float lo, hi; asm("mov.b64 {%0,%1},%2;" : "=f"(lo), "=f"(hi) : "l"(a)); return lo + hi;
}
__device__ __forceinline__ void sts32(unsigned a, float v) {
    asm volatile("st.shared.f32 [%0],%1;" :: "r"(a), "f"(v));
}
__device__ __forceinline__ void sts64(unsigned a, u64 v) {
    asm volatile("st.shared.u64 [%0],%1;" :: "r"(a), "l"(v));
}
__device__ __forceinline__ float tanh_fast(float x) {
    float y; asm("tanh.approx.f32 %0,%1;" : "=f"(y) : "f"(x)); return y;
}

// swizzled word offset for Wd arrays: row r, float k. 16B chunks rotated by (r&7)
__device__ __forceinline__ int wd_off(int r, int k) {
    const int c = k >> 2, j = k & 3;
    const int hc = c >> 3, c8 = c & 7;
    return r * 64 + hc * 32 + (((c8 + r) & 7) << 2) + j;
}

__device__ __forceinline__ void gnn_layer(float* __restrict__ sm, unsigned sb,
                                          int t, int lane, int w,
                                          int wroff, int boff, int wdoff)
{
    // ---- colsum[g][k] = sum over 9 nodes (256 threads: 32 g x 8 k-chunks) ----
    if (t < 256) {
        const int g = t >> 3, kq = t & 7;
        const float* a = sm + OFF_H + g * 9 * HS + kq * 8;
        u64 s0 = *(const u64*)(a);
        u64 s1 = *(const u64*)(a + 2);
        u64 s2 = *(const u64*)(a + 4);
        u64 s3 = *(const u64*)(a + 6);
        #pragma unroll
        for (int n = 1; n < 9; n++) {
            const float* r = a + n * HS;
            s0 = fadd2(s0, *(const u64*)(r));
            s1 = fadd2(s1, *(const u64*)(r + 2));
            s2 = fadd2(s2, *(const u64*)(r + 4));
            s3 = fadd2(s3, *(const u64*)(r + 6));
        }
        const unsigned o = sb + (unsigned)(OFF_CS + g * CSS + kq * 8) * 4u;
        sts64(o, s0); sts64(o + 8, s1); sts64(o + 16, s2); sts64(o + 24, s3);
    }
    __syncthreads();

    // ---- S[g][d] = b[d] + CS[g] . Wrel[d]  (warps 0..7: warp=d-set, lane=g) ----
    if (t < 256) {
        const int g = lane;
        u64 c[32];
        const float* cr = sm + OFF_CS + g * CSS;
        #pragma unroll
        for (int q = 0; q < 32; q++) c[q] = *(const u64*)(cr + q * 2);
        #pragma unroll 2
        for (int i = 0; i < 8; i++) {
            const int d = w * 8 + i;
            const float* wr = sm + wroff + d * 64;
            u64 a0 = 0, a1 = 0, a2 = 0, a3 = 0;
            #pragma unroll
            for (int q = 0; q < 8; q++) {
                const ulonglong2 wv0 = *(const ulonglong2*)(wr + q * 8);
                const ulonglong2 wv1 = *(const ulonglong2*)(wr + q * 8 + 4);
                a0 = ffma2(wv0.x, c[4*q],   a0);
                a1 = ffma2(wv0.y, c[4*q+1], a1);
                a2 = ffma2(wv1.x, c[4*q+2], a2);
                a3 = ffma2(wv1.y, c[4*q+3], a3);
            }
            const float sv = sm[boff + d]
                           + red2(fadd2(fadd2(a0, a1), fadd2(a2, a3)));
            sts32(sb + (unsigned)(OFF_S + g * SS + d) * 4u, sv);
        }
    }
    __syncthreads();

    // ---- transform: h'[n] = tanh(S[g(n)] + h[n] @ Wd^T), weights lane-stationary,
    //      2 nodes per iteration for ILP/MLP ----
    {
        u64 wa[32], wb[32];
        const float* wbase = sm + wdoff;
        #pragma unroll
        for (int c = 0; c < 16; c++) {
            const int hc = c >> 3;
            const int rot = ((c & 7) + lane) & 7;
            const ulonglong2 va = *(const ulonglong2*)(wbase + lane * 64 + hc * 32 + rot * 4);
            const ulonglong2 vb = *(const ulonglong2*)(wbase + (lane + 32) * 64 + hc * 32 + rot * 4);
            wa[2*c] = va.x; wa[2*c+1] = va.y;
            wb[2*c] = vb.x; wb[2*c+1] = vb.y;
        }

        const int n0 = w * NPW;
        int g = (n0 * 7282) >> 16;            // n0/9 for n0<576
        int rem = n0 - g * 9;
        const float* hb = sm + OFF_H + n0 * HS;
        unsigned hr = sb + (unsigned)(OFF_H + n0 * HS) * 4u;

        #pragma unroll 1
        for (int it = 0; it < NPW / 2; it++) {
            const float* h0 = hb + (2 * it) * HS;
            const float* h1 = h0 + HS;
            u64 a0 = 0, a1 = 0, b0 = 0, b1 = 0;
            u64 c0 = 0, c1 = 0, d0 = 0, d1 = 0;
            #pragma unroll
            for (int q = 0; q < 16; q++) {
                const ulonglong2 v0 = *(const ulonglong2*)(h0 + q * 4);
                const ulonglong2 v1 = *(const ulonglong2*)(h1 + q * 4);
                a0 = ffma2(wa[2*q],   v0.x, a0);
                a1 = ffma2(wa[2*q+1], v0.y, a1);
                b0 = ffma2(wb[2*q],   v0.x, b0);
                b1 = ffma2(wb[2*q+1], v0.y, b1);
                c0 = ffma2(wa[2*q],   v1.x, c0);
                c1 = ffma2(wa[2*q+1], v1.y, c1);
                d0 = ffma2(wb[2*q],   v1.x, d0);
                d1 = ffma2(wb[2*q+1], v1.y, d1);
            }
            // node 2*it
            {
                const float* Srow = sm + OFF_S + g * SS;
                const float va = tanh_fast(red2(fadd2(a0, a1)) + Srow[lane]);
                const float vb = tanh_fast(red2(fadd2(b0, b1)) + Srow[lane + 32]);
                sts32(hr + (unsigned)lane * 4u, va);
                sts32(hr + (unsigned)(lane + 32) * 4u, vb);
                hr += HS * 4u;
                if (++rem == 9) { rem = 0; g++; }
            }
            // node 2*it+1
            {
                const float* Srow = sm + OFF_S + g * SS;
                const float va = tanh_fast(red2(fadd2(c0, c1)) + Srow[lane]);
                const float vb = tanh_fast(red2(fadd2(d0, d1)) + Srow[lane + 32]);
                sts32(hr + (unsigned)lane * 4u, va);
                sts32(hr + (unsigned)(lane + 32) * 4u, vb);
                hr += HS * 4u;
                if (++rem == 9) { rem = 0; g++; }
            }
        }
    }
    __syncthreads();
}

__global__ __launch_bounds__(TPB, 1)
void gnn_kernel(const float* __restrict__ x,
                const float* __restrict__ gWin,  const float* __restrict__ gbin,
                const float* __restrict__ gW1rel, const float* __restrict__ gb1,
                const float* __restrict__ gW1root,
                const float* __restrict__ gW2rel, const float* __restrict__ gb2,
                const float* __restrict__ gW2root,
                const float* __restrict__ gWhead, const float* __restrict__ gbhead,
                float* __restrict__ out)
{
    extern __shared__ float sm[];
    const unsigned sb = (unsigned)__cvta_generic_to_shared(sm);
    const int t = threadIdx.x;
    const int lane = t & 31, w = t >> 5;

    // ---- one-time staging ----
    for (int i = t; i < 4096; i += TPB) {
        const int d = i >> 6, k = i & 63;
        const int so = wd_off(d, k);
        const float r1 = gW1rel[i];
        sm[OFF_WR1 + i]  = r1;
        sm[OFF_WD1 + so] = gW1root[i] - r1;
        const float r2 = gW2rel[i];
        sm[OFF_WR2 + i]  = r2;
        sm[OFF_WD2 + so] = gW2root[i] - r2;
    }
    for (int i = t; i < 768; i += TPB) {
        const int d = i / 12, k = i - d * 12;
        sm[OFF_WIN + i] = (k < 11) ? gWin[d * 11 + k] : 0.f;
    }
    for (int i = t; i < 1024; i += TPB) {
        const int j = i >> 7, r = i & 127, k = r >> 1, o = r & 1;
        sm[OFF_WHT + (j * 2 + o) * 64 + k] = gWhead[i];
    }
    if (t < 64) { sm[OFF_BIN + t] = gbin[t]; sm[OFF_B1 + t] = gb1[t]; sm[OFF_B2 + t] = gb2[t]; }
    if (t < 16) sm[OFF_BH + t] = gbhead[t];
    if (t < 288) sm[OFF_XS + t * 12 + 11] = 0.f;   // x pad column, persists
    __syncthreads();

    for (int tile = blockIdx.x; tile < NTILES; tile += gridDim.x) {
        // ---- stage x coalesced ----
        const float* xg = x + (long long)tile * (NODES * 11);
        for (int i = t; i < NODES * 11; i += TPB) {
            const int n = (i * 5958) >> 16;      // i/11 for i<3168
            sm[OFF_XS + n * 12 + (i - n * 11)] = xg[i];
        }
        __syncthreads();

        // ---- input layer: register-stationary weights, x broadcast, 2 nodes/iter ----
        {
            u64 wi[12];
            const float* wr0 = sm + OFF_WIN + lane * 12;
            const float* wr1 = sm + OFF_WIN + (lane + 32) * 12;
            #pragma unroll
            for (int q = 0; q < 3; q++) {
                const ulonglong2 v0 = *(const ulonglong2*)(wr0 + q * 4);
                const ulonglong2 v1 = *(const ulonglong2*)(wr1 + q * 4);
                wi[2*q] = v0.x;   wi[2*q+1] = v0.y;
                wi[6+2*q] = v1.x; wi[6+2*q+1] = v1.y;
            }
            const float bi0 = sm[OFF_BIN + lane], bi1 = sm[OFF_BIN + lane + 32];

            const float* xr = sm + OFF_XS + w * NPW * 12;
            unsigned hw = sb + (unsigned)(OFF_H + w * NPW * HS) * 4u;
            #pragma unroll 1
            for (int it = 0; it < NPW / 2; it++) {
                const float* x0 = xr + (2 * it) * 12;
                const float* x1 = x0 + 12;
                u64 a0 = 0, a1 = 0, b0 = 0, b1 = 0;
                #pragma unroll
                for (int q = 0; q < 3; q++) {
                    const ulonglong2 v0 = *(const ulonglong2*)(x0 + q * 4);
                    const ulonglong2 v1 = *(const ulonglong2*)(x1 + q * 4);
                    a0 = ffma2(wi[2*q],   v0.x, a0);
                    a0 = ffma2(wi[2*q+1], v0.y, a0);
                    a1 = ffma2(wi[6+2*q],   v0.x, a1);
                    a1 = ffma2(wi[6+2*q+1], v0.y, a1);
                    b0 = ffma2(wi[2*q],   v1.x, b0);
                    b0 = ffma2(wi[2*q+1], v1.y, b0);
                    b1 = ffma2(wi[6+2*q],   v1.x, b1);
                    b1 = ffma2(wi[6+2*q+1], v1.y, b1);
                }
                sts32(hw + (unsigned)lane * 4u,        red2(a0) + bi0);
                sts32(hw + (unsigned)(lane + 32) * 4u, red2(a1) + bi1);
                hw += HS * 4u;
                sts32(hw + (unsigned)lane * 4u,        red2(b0) + bi0);
                sts32(hw + (unsigned)(lane + 32) * 4u, red2(b1) + bi1);
                hw += HS * 4u;
            }
        }
        __syncthreads();

        gnn_layer(sm, sb, t, lane, w, OFF_WR1, OFF_B1, OFF_WD1);
        gnn_layer(sm, sb, t, lane, w, OFF_WR2, OFF_B2, OFF_WD2);

        // ---- heads: warp w = node j (0..7), lane = graph ----
        if (t < 256) {
            u64 h[32];
            const float* hr = sm + OFF_H + (lane * 9 + w + 1) * HS;
            #pragma unroll
            for (int q = 0; q < 32; q++) h[q] = *(const u64*)(hr + q * 2);
            float res[2];
            #pragma unroll
            for (int o = 0; o < 2; o++) {
                const float* wr = sm + OFF_WHT + (w * 2 + o) * 64;
                u64 a0 = 0, a1 = 0, a2 = 0, a3 = 0;
                #pragma unroll
                for (int q = 0; q < 8; q++) {
                    const ulonglong2 w0 = *(const ulonglong2*)(wr + q * 8);
                    const ulonglong2 w1 = *(const ulonglong2*)(wr + q * 8 + 4);
                    a0 = ffma2(w0.x, h[4*q],   a0);
                    a1 = ffma2(w0.y, h[4*q+1], a1);
                    a2 = ffma2(w1.x, h[4*q+2], a2);
                    a3 = ffma2(w1.y, h[4*q+3], a3);
                }
                res[o] = sm[OFF_BH + w * 2 + o]
                       + red2(fadd2(fadd2(a0, a1), fadd2(a2, a3)));
            }
            const long long gi = (long long)(tile * G + lane) * 8 + w;
            out[gi] = res[0];
            const float z = res[1] + SOFTPLUS_BIAS;
            const float sp = (z > 20.f) ? z : log1pf(__expf(z));
            out[TOTOUT + gi] = fmaxf(sp, 1e-4f);
        }
    }
}

extern "C" void kernel_launch(void* const* d_in, const int* in_sizes, int n_in,
                              void* d_out, int out_size)
{
    (void)in_sizes; (void)n_in; (void)out_size;
    const float* x      = (const float*)d_in[0];
    // d_in[1] = edge_index: dense 9-node graphs, structurally known -> unused
    const float* W_in   = (const float*)d_in[2];
    const float* b_in   = (const float*)d_in[3];
    const float* W1_rel = (const float*)d_in[4];
    const float* b1     = (const float*)d_in[5];
    const float* W1_root= (const float*)d_in[6];
    const float* W2_rel = (const float*)d_in[7];
    const float* b2     = (const float*)d_in[8];
    const float* W2_root= (const float*)d_in[9];
    const float* W_head = (const float*)d_in[10];
    const float* b_head = (const float*)d_in[11];
    float* out = (float*)d_out;

    int nsm = 148;
    cudaDeviceGetAttribute(&nsm, cudaDevAttrMultiProcessorCount, 0);

    const int smem = SMEM_FLOATS * 4;
    cudaFuncSetAttribute(gnn_kernel, cudaFuncAttributeMaxDynamicSharedMemorySize, smem);
    gnn_kernel<<<nsm, TPB, smem>>>(x, W_in, b_in, W1_rel, b1, W1_root,
                                   W2_rel, b2, W2_root, W_head, b_head, out);
}

// round 7
// speedup vs baseline: 1.6364x; 1.2458x over previous
#include <cuda_runtime.h>
#include <math.h>

#define TPB 384               // 12 warps, warp-autonomous
#define NW 12
#define NUNITS 16384          // 65536 graphs / 4 per unit
#define NPU 36                // nodes per unit
#define TOTOUT 524288
#define SOFTPLUS_BIAS 0.54132485461291809f

// shared layout (float offsets)
#define OFF_WD1 0             // [64][64] swizzled (Wroot - Wrel)
#define OFF_WD2 4096
#define OFF_WR1 8192          // [64][64] swizzled Wrel
#define OFF_WR2 12288
#define OFF_WIN 16384         // [64][12]
#define OFF_WHT 17152         // [16][68]
#define OFF_BIN 18240
#define OFF_B1  18304
#define OFF_B2  18368
#define OFF_BH  18432         // [16]
#define OFF_WARP 18448        // per-warp scratch base
#define WPS 2992              // per-warp floats: hws[36][68]=2448 + aux 544
#define SMEM_FLOATS (OFF_WARP + NW * WPS)   // 54352 floats = 217,408 B

typedef unsigned long long u64;

__device__ __forceinline__ u64 ffma2(u64 a, u64 b, u64 c) {
    u64 d; asm("fma.rn.f32x2 %0,%1,%2,%3;" : "=l"(d) : "l"(a), "l"(b), "l"(c)); return d;
}
__device__ __forceinline__ u64 fadd2(u64 a, u64 b) {
    u64 d; asm("add.rn.f32x2 %0,%1,%2;" : "=l"(d) : "l"(a), "l"(b)); return d;
}
__device__ __forceinline__ float red2(u64 a) {
    float lo, hi; asm("mov.b64 {%0,%1},%2;" : "=f"(lo), "=f"(hi) : "l"(a)); return lo + hi;
}
__device__ __forceinline__ float tanh_fast(float x) {
    float y; asm("tanh.approx.f32 %0,%1;" : "=f"(y) : "f"(x)); return y;
}

// swizzled word offset: row r, float k; 16B chunks rotated by (r&7) within 128B halves
__device__ __forceinline__ int wd_off(int r, int k) {
    const int c = k >> 2, j = k & 3;
    const int hc = c >> 3, c8 = c & 7;
    return r * 64 + hc * 32 + (((c8 + r) & 7) << 2) + j;
}

__global__ __launch_bounds__(TPB, 1)
void gnn_kernel(const float* __restrict__ x,
                const float* __restrict__ gWin,  const float* __restrict__ gbin,
                const float* __restrict__ gW1rel, const float* __restrict__ gb1,
                const float* __restrict__ gW1root,
                const float* __restrict__ gW2rel, const float* __restrict__ gb2,
                const float* __restrict__ gW2root,
                const float* __restrict__ gWhead, const float* __restrict__ gbhead,
                float* __restrict__ out)
{
    extern __shared__ float sm[];
    const int t = threadIdx.x;
    const int lane = t & 31, w = t >> 5;

    // ---- one-time weight staging (both Wrel and Wd swizzled) ----
    for (int i = t; i < 4096; i += TPB) {
        const int d = i >> 6, k = i & 63;
        const int so = wd_off(d, k);
        const float r1 = gW1rel[i];
        sm[OFF_WR1 + so] = r1;
        sm[OFF_WD1 + so] = gW1root[i] - r1;
        const float r2 = gW2rel[i];
        sm[OFF_WR2 + so] = r2;
        sm[OFF_WD2 + so] = gW2root[i] - r2;
    }
    for (int i = t; i < 768; i += TPB) {
        const int d = i / 12, k = i - d * 12;
        sm[OFF_WIN + i] = (k < 11) ? gWin[d * 11 + k] : 0.f;
    }
    for (int i = t; i < 1024; i += TPB) {
        const int j = i >> 7, r = i & 127, k = r >> 1, o = r & 1;
        sm[OFF_WHT + (j * 2 + o) * 68 + k] = gWhead[i];
    }
    if (t < 64) { sm[OFF_BIN + t] = gbin[t]; sm[OFF_B1 + t] = gb1[t]; sm[OFF_B2 + t] = gb2[t]; }
    if (t < 16) sm[OFF_BH + t] = gbhead[t];
    __syncthreads();   // only block-wide barrier in the kernel

    float* const hws  = sm + OFF_WARP + w * WPS;   // [36][68]
    float* const aux  = hws + 2448;
    float* const xs   = aux;                        // [36][12]  (overlaid)
    float* const csws = aux;                        // [4][68]   (written after x consumed)
    float* const Sws  = aux + 272;                  // [4][68]

    const float bi0 = sm[OFF_BIN + lane], bi1 = sm[OFF_BIN + lane + 32];

    for (unsigned unit = blockIdx.x * NW + w; unit < NUNITS; unit += gridDim.x * NW) {
        // ---- stage x: 396 contiguous floats, warp-coalesced ----
        const float* xg = x + (size_t)unit * (NPU * 11);
        #pragma unroll
        for (int q = 0; q < 13; q++) {
            const int i = lane + q * 32;
            if (q < 12 || i < NPU * 11) {
                const float v = xg[i];
                const int n = (i * 5958) >> 16;        // i/11 (i < 3168)
                xs[n * 12 + (i - n * 11)] = v;
            }
        }
        xs[lane * 12 + 11] = 0.f;                      // pad col (rows 0..31)
        if (lane < 4) xs[(32 + lane) * 12 + 11] = 0.f; // rows 32..35
        __syncwarp();

        // ---- input layer: h = x @ Win^T + b; accumulate colsum in registers ----
        {
            u64 wi[12];
            #pragma unroll
            for (int q = 0; q < 3; q++) {
                const ulonglong2 v0 = *(const ulonglong2*)(sm + OFF_WIN + lane * 12 + q * 4);
                const ulonglong2 v1 = *(const ulonglong2*)(sm + OFF_WIN + (lane + 32) * 12 + q * 4);
                wi[2*q] = v0.x;   wi[2*q+1] = v0.y;
                wi[6+2*q] = v1.x; wi[6+2*q+1] = v1.y;
            }
            #pragma unroll 1
            for (int g = 0; g < 4; g++) {
                float cs0 = 0.f, cs1 = 0.f;
                const float* xb = xs + g * 9 * 12;
                float* hb = hws + g * 9 * 68;
                #pragma unroll
                for (int p = 0; p < 4; p++) {
                    const float* x0 = xb + 2 * p * 12;
                    const float* x1 = x0 + 12;
                    u64 A = 0, B = 0, C = 0, D = 0;
                    #pragma unroll
                    for (int q = 0; q < 3; q++) {
                        const ulonglong2 v0 = *(const ulonglong2*)(x0 + q * 4);
                        const ulonglong2 v1 = *(const ulonglong2*)(x1 + q * 4);
                        A = ffma2(wi[2*q], v0.x, A);   A = ffma2(wi[2*q+1], v0.y, A);
                        B = ffma2(wi[6+2*q], v0.x, B); B = ffma2(wi[6+2*q+1], v0.y, B);
                        C = ffma2(wi[2*q], v1.x, C);   C = ffma2(wi[2*q+1], v1.y, C);
                        D = ffma2(wi[6+2*q], v1.x, D); D = ffma2(wi[6+2*q+1], v1.y, D);
                    }
                    const float h00 = red2(A) + bi0, h01 = red2(B) + bi1;
                    const float h10 = red2(C) + bi0, h11 = red2(D) + bi1;
                    hb[(2*p) * 68 + lane] = h00;      hb[(2*p) * 68 + lane + 32] = h01;
                    hb[(2*p+1) * 68 + lane] = h10;    hb[(2*p+1) * 68 + lane + 32] = h11;
                    cs0 += h00 + h10; cs1 += h01 + h11;
                }
                {   // node 8
                    const float* x0 = xb + 8 * 12;
                    u64 A = 0, B = 0;
                    #pragma unroll
                    for (int q = 0; q < 3; q++) {
                        const ulonglong2 v0 = *(const ulonglong2*)(x0 + q * 4);
                        A = ffma2(wi[2*q], v0.x, A);   A = ffma2(wi[2*q+1], v0.y, A);
                        B = ffma2(wi[6+2*q], v0.x, B); B = ffma2(wi[6+2*q+1], v0.y, B);
                    }
                    const float h00 = red2(A) + bi0, h01 = red2(B) + bi1;
                    hb[8 * 68 + lane] = h00; hb[8 * 68 + lane + 32] = h01;
                    cs0 += h00; cs1 += h01;
                }
                csws[g * 68 + lane] = cs0;
                csws[g * 68 + lane + 32] = cs1;
            }
        }
        __syncwarp();

        // ---- two GraphConv layers, fully warp-local ----
        #pragma unroll 1
        for (int layer = 0; layer < 2; layer++) {
            const float* WR = sm + (layer ? OFF_WR2 : OFF_WR1);
            const float* WD = sm + (layer ? OFF_WD2 : OFF_WD1);
            const float* BB = sm + (layer ? OFF_B2 : OFF_B1);

            // S[g][d] = b[d] + cs[g] . Wrel[d]   (lane owns d = lane, lane+32)
            {
                u64 SA[4] = {0,0,0,0}, SB[4] = {0,0,0,0};
                #pragma unroll
                for (int c = 0; c < 16; c++) {
                    const int hc = c >> 3;
                    const int rot = ((c & 7) + lane) & 7;
                    const ulonglong2 wlo = *(const ulonglong2*)(WR + lane * 64 + hc * 32 + rot * 4);
                    const ulonglong2 whi = *(const ulonglong2*)(WR + (lane + 32) * 64 + hc * 32 + rot * 4);
                    #pragma unroll
                    for (int g = 0; g < 4; g++) {
                        const u64 c0 = *(const u64*)(csws + g * 68 + c * 4);
                        const u64 c1 = *(const u64*)(csws + g * 68 + c * 4 + 2);
                        SA[g] = ffma2(wlo.x, c0, SA[g]); SA[g] = ffma2(wlo.y, c1, SA[g]);
                        SB[g] = ffma2(whi.x, c0, SB[g]); SB[g] = ffma2(whi.y, c1, SB[g]);
                    }
                }
                const float blo = BB[lane], bhi = BB[lane + 32];
                #pragma unroll
                for (int g = 0; g < 4; g++) {
                    Sws[g * 68 + lane]      = blo + red2(SA[g]);
                    Sws[g * 68 + lane + 32] = bhi + red2(SB[g]);
                }
            }
            __syncwarp();

            // lane-stationary Wd rows (conflict-free via swizzle rotation)
            u64 wa[32], wb[32];
            #pragma unroll
            for (int c = 0; c < 16; c++) {
                const int hc = c >> 3;
                const int rot = ((c & 7) + lane) & 7;
                const ulonglong2 va = *(const ulonglong2*)(WD + lane * 64 + hc * 32 + rot * 4);
                const ulonglong2 vb = *(const ulonglong2*)(WD + (lane + 32) * 64 + hc * 32 + rot * 4);
                wa[2*c] = va.x; wa[2*c+1] = va.y;
                wb[2*c] = vb.x; wb[2*c+1] = vb.y;
            }

            // transform: h'[n] = tanh(S[g] + h[n] @ Wd^T); colsum accumulated in regs
            #pragma unroll 1
            for (int g = 0; g < 4; g++) {
                const float S0 = Sws[g * 68 + lane];
                const float S1 = Sws[g * 68 + lane + 32];
                float cs0 = 0.f, cs1 = 0.f;
                float* hb = hws + g * 9 * 68;
                #pragma unroll
                for (int p = 0; p < 4; p++) {
                    const float* h0 = hb + 2 * p * 68;
                    const float* h1 = h0 + 68;
                    u64 A0=0,A1=0,B0=0,B1=0,C0=0,C1=0,D0=0,D1=0;
                    #pragma unroll
                    for (int q = 0; q < 16; q++) {
                        const ulonglong2 v0 = *(const ulonglong2*)(h0 + q * 4);
                        const ulonglong2 v1 = *(const ulonglong2*)(h1 + q * 4);
                        A0 = ffma2(wa[2*q],   v0.x, A0);
                        A1 = ffma2(wa[2*q+1], v0.y, A1);
                        B0 = ffma2(wb[2*q],   v0.x, B0);
                        B1 = ffma2(wb[2*q+1], v0.y, B1);
                        C0 = ffma2(wa[2*q],   v1.x, C0);
                        C1 = ffma2(wa[2*q+1], v1.y, C1);
                        D0 = ffma2(wb[2*q],   v1.x, D0);
                        D1 = ffma2(wb[2*q+1], v1.y, D1);
                    }
                    __syncwarp();   // all lanes' reads of rows 2p,2p+1 done before overwrite
                    const float h00 = tanh_fast(red2(fadd2(A0, A1)) + S0);
                    const float h01 = tanh_fast(red2(fadd2(B0, B1)) + S1);
                    const float h10 = tanh_fast(red2(fadd2(C0, C1)) + S0);
                    const float h11 = tanh_fast(red2(fadd2(D0, D1)) + S1);
                    hb[(2*p) * 68 + lane] = h00;    hb[(2*p) * 68 + lane + 32] = h01;
                    hb[(2*p+1) * 68 + lane] = h10;  hb[(2*p+1) * 68 + lane + 32] = h11;
                    cs0 += h00 + h10; cs1 += h01 + h11;
                }
                {   // node 8
                    const float* h0 = hb + 8 * 68;
                    u64 A0=0,A1=0,B0=0,B1=0;
                    #pragma unroll
                    for (int q = 0; q < 16; q++) {
                        const ulonglong2 v0 = *(const ulonglong2*)(h0 + q * 4);
                        A0 = ffma2(wa[2*q],   v0.x, A0);
                        A1 = ffma2(wa[2*q+1], v0.y, A1);
                        B0 = ffma2(wb[2*q],   v0.x, B0);
                        B1 = ffma2(wb[2*q+1], v0.y, B1);
                    }
                    __syncwarp();
                    const float h00 = tanh_fast(red2(fadd2(A0, A1)) + S0);
                    const float h01 = tanh_fast(red2(fadd2(B0, B1)) + S1);
                    hb[8 * 68 + lane] = h00; hb[8 * 68 + lane + 32] = h01;
                    cs0 += h00; cs1 += h01;
                }
                csws[g * 68 + lane] = cs0;          // safe: this layer's S already consumed
                csws[g * 68 + lane + 32] = cs1;
            }
            __syncwarp();
        }

        // ---- heads: lane = (graph-half gh, node j, output o); 2 graphs per lane ----
        {
            const int gh = lane >> 4, j = (lane >> 1) & 7, o = lane & 1;
            const float* whr = sm + OFF_WHT + (j * 2 + o) * 68;
            const float bh = sm[OFF_BH + j * 2 + o];
            #pragma unroll
            for (int gl = 0; gl < 2; gl++) {
                const int graph = gl * 2 + gh;
                const float* hr = hws + (graph * 9 + j + 1) * 68;
                u64 A0=0,A1=0,A2=0,A3=0;
                #pragma unroll
                for (int q = 0; q < 8; q++) {
                    const ulonglong2 wv = *(const ulonglong2*)(whr + q * 8);
                    const ulonglong2 wv2 = *(const ulonglong2*)(whr + q * 8 + 4);
                    const ulonglong2 hv = *(const ulonglong2*)(hr + q * 8);
                    const ulonglong2 hv2 = *(const ulonglong2*)(hr + q * 8 + 4);
                    A0 = ffma2(wv.x,  hv.x,  A0);
                    A1 = ffma2(wv.y,  hv.y,  A1);
                    A2 = ffma2(wv2.x, hv2.x, A2);
                    A3 = ffma2(wv2.y, hv2.y, A3);
                }
                const float r = bh + red2(fadd2(fadd2(A0, A1), fadd2(A2, A3)));
                const size_t gi = (size_t)(unit * 4 + graph) * 8 + j;
                if (o == 0) {
                    out[gi] = r;
                } else {
                    const float z = r + SOFTPLUS_BIAS;
                    const float sp = (z > 20.f) ? z : log1pf(__expf(z));
                    out[TOTOUT + gi] = fmaxf(sp, 1e-4f);
                }
            }
        }
        // next iteration's x staging is ordered after head reads by the post-staging __syncwarp
    }
}

extern "C" void kernel_launch(void* const* d_in, const int* in_sizes, int n_in,
                              void* d_out, int out_size)
{
    (void)in_sizes; (void)n_in; (void)out_size;
    const float* x      = (const float*)d_in[0];
    // d_in[1] = edge_index: dense 9-node graphs, structurally known -> unused
    const float* W_in   = (const float*)d_in[2];
    const float* b_in   = (const float*)d_in[3];
    const float* W1_rel = (const float*)d_in[4];
    const float* b1     = (const float*)d_in[5];
    const float* W1_root= (const float*)d_in[6];
    const float* W2_rel = (const float*)d_in[7];
    const float* b2     = (const float*)d_in[8];
    const float* W2_root= (const float*)d_in[9];
    const float* W_head = (const float*)d_in[10];
    const float* b_head = (const float*)d_in[11];
    float* out = (float*)d_out;

    int nsm = 148;
    cudaDeviceGetAttribute(&nsm, cudaDevAttrMultiProcessorCount, 0);

    const int smem = SMEM_FLOATS * 4;
    cudaFuncSetAttribute(gnn_kernel, cudaFuncAttributeMaxDynamicSharedMemorySize, smem);
    gnn_kernel<<<nsm, TPB, smem>>>(x, W_in, b_in, W1_rel, b1, W1_root,
                                   W2_rel, b2, W2_root, W_head, b_head, out);
}